// round 11
// baseline (speedup 1.0000x reference)
#include <cuda_runtime.h>
#include <cuda_bf16.h>
#include <cstdint>

#define B_  4
#define T_  2048
#define C_  768
#define NH  12
#define HS  64
#define M_  (B_ * T_)          // 8192
#define N1  (3 * C_)           // 2304
#define KD  C_                 // 768
#define C3  (3 * C_)

// ---------------- scratch (__device__ globals; no cudaMalloc) --------------
__device__ __align__(256) __nv_bfloat16 g_xh  [M_ * KD], g_xl  [M_ * KD];
__device__ __align__(256) __nv_bfloat16 g_qkvh[M_ * N1], g_qkvl[M_ * N1];
__device__ __align__(256) __nv_bfloat16 g_yh  [M_ * KD], g_yl  [M_ * KD];
__device__ __align__(256) __nv_bfloat16 g_wah [N1 * KD], g_wal [N1 * KD];  // w_attn^T [N,K]
__device__ __align__(256) __nv_bfloat16 g_wph [C_ * KD], g_wpl [C_ * KD];  // w_proj^T [N,K]

// ---------------- helpers ---------------------------------------------------
__device__ __forceinline__ uint32_t smem_u32(const void* p) {
    uint32_t a;
    asm("{ .reg .u64 t; cvta.to.shared.u64 t, %1; cvt.u32.u64 %0, t; }"
        : "=r"(a) : "l"(p));
    return a;
}
__device__ __forceinline__ uint32_t swz(uint32_t off) {     // SW128
    return off ^ ((off >> 3) & 0x70);
}
__device__ __forceinline__ void cp16(uint32_t dst, const void* src) {
    asm volatile("cp.async.cg.shared.global [%0], [%1], 16;" :: "r"(dst), "l"(src));
}
#define CP_COMMIT() asm volatile("cp.async.commit_group;" ::: "memory")
#define CP_WAIT1()  asm volatile("cp.async.wait_group 1;" ::: "memory")

__device__ __forceinline__ void ldsm4(uint32_t& r0, uint32_t& r1,
                                      uint32_t& r2, uint32_t& r3, uint32_t a) {
    asm volatile("ldmatrix.sync.aligned.m8n8.x4.shared.b16 {%0,%1,%2,%3}, [%4];"
                 : "=r"(r0), "=r"(r1), "=r"(r2), "=r"(r3) : "r"(a));
}
__device__ __forceinline__ void ldsm4t(uint32_t& r0, uint32_t& r1,
                                       uint32_t& r2, uint32_t& r3, uint32_t a) {
    asm volatile("ldmatrix.sync.aligned.m8n8.x4.trans.shared.b16 {%0,%1,%2,%3}, [%4];"
                 : "=r"(r0), "=r"(r1), "=r"(r2), "=r"(r3) : "r"(a));
}
__device__ __forceinline__ void mma16816(float* d, const uint32_t* a,
                                         const uint32_t* b) {
    asm volatile("mma.sync.aligned.m16n8k16.row.col.f32.bf16.bf16.f32 "
                 "{%0,%1,%2,%3}, {%4,%5,%6,%7}, {%8,%9}, {%0,%1,%2,%3};"
                 : "+f"(d[0]), "+f"(d[1]), "+f"(d[2]), "+f"(d[3])
                 : "r"(a[0]), "r"(a[1]), "r"(a[2]), "r"(a[3]),
                   "r"(b[0]), "r"(b[1]));
}
__device__ __forceinline__ float ex2f(float x) {
    float y; asm("ex2.approx.f32 %0, %1;" : "=f"(y) : "f"(x)); return y;
}
__device__ __forceinline__ void split_pack(float a, float b,
                                           uint32_t& hi, uint32_t& lo) {
    __nv_bfloat16 ha = __float2bfloat16(a), hb = __float2bfloat16(b);
    __nv_bfloat16 la = __float2bfloat16(a - __bfloat162float(ha));
    __nv_bfloat16 lb = __float2bfloat16(b - __bfloat162float(hb));
    __nv_bfloat162 H(ha, hb), L(la, lb);
    hi = *reinterpret_cast<uint32_t*>(&H);
    lo = *reinterpret_cast<uint32_t*>(&L);
}

// ---------------- split conversion kernels ---------------------------------
__global__ __launch_bounds__(256) void split_cvt(
    const float* __restrict__ in, __nv_bfloat16* __restrict__ hi,
    __nv_bfloat16* __restrict__ lo, int n)
{
    int idx = (blockIdx.x * 256 + threadIdx.x) * 4;
    if (idx >= n) return;
    float4 v = *reinterpret_cast<const float4*>(in + idx);
    __nv_bfloat16 h0 = __float2bfloat16(v.x), h1 = __float2bfloat16(v.y);
    __nv_bfloat16 h2 = __float2bfloat16(v.z), h3 = __float2bfloat16(v.w);
    __nv_bfloat16 l0 = __float2bfloat16(v.x - __bfloat162float(h0));
    __nv_bfloat16 l1 = __float2bfloat16(v.y - __bfloat162float(h1));
    __nv_bfloat16 l2 = __float2bfloat16(v.z - __bfloat162float(h2));
    __nv_bfloat16 l3 = __float2bfloat16(v.w - __bfloat162float(h3));
    *reinterpret_cast<__nv_bfloat162*>(hi + idx)     = __nv_bfloat162(h0, h1);
    *reinterpret_cast<__nv_bfloat162*>(hi + idx + 2) = __nv_bfloat162(h2, h3);
    *reinterpret_cast<__nv_bfloat162*>(lo + idx)     = __nv_bfloat162(l0, l1);
    *reinterpret_cast<__nv_bfloat162*>(lo + idx + 2) = __nv_bfloat162(l2, l3);
}

// transpose + split: in [K,N] row-major -> hi/lo [N,K]
__global__ __launch_bounds__(256) void split_cvt_T(
    const float* __restrict__ in, __nv_bfloat16* __restrict__ hi,
    __nv_bfloat16* __restrict__ lo, int K, int N)
{
    __shared__ float t[32][33];
    const int tx = threadIdx.x & 31, ty = threadIdx.x >> 5;
    const int k0 = blockIdx.y * 32, n0 = blockIdx.x * 32;
#pragma unroll
    for (int r = 0; r < 32; r += 8)
        t[ty + r][tx] = in[(size_t)(k0 + ty + r) * N + n0 + tx];
    __syncthreads();
#pragma unroll
    for (int r = 0; r < 32; r += 8) {
        float v = t[tx][ty + r];
        __nv_bfloat16 h = __float2bfloat16(v);
        __nv_bfloat16 l = __float2bfloat16(v - __bfloat162float(h));
        size_t o = (size_t)(n0 + ty + r) * K + k0 + tx;
        hi[o] = h; lo[o] = l;
    }
}

// ---------------- mma.sync split-bf16 GEMM ----------------------------------
// Single-barrier 3-stage pipeline: prologue fills 2 stages; each iter
// pre-issues chunk c+2 into the buffer freed by compute(c-1) (barrier-proven),
// then computes chunk c.  One __syncthreads per chunk.
#define GBK   64
#define TILEB (128 * 128)
#define STAGEB (4 * TILEB)
#define STAGES 3
#define GSMEM (STAGES * STAGEB)  // 192KB

__device__ __forceinline__ void load_op(
    const __nv_bfloat16* __restrict__ g, int row0, int K, int k0,
    uint32_t sdst, int tid)
{
#pragma unroll
    for (int t = 0; t < 4; t++) {
        int idx = tid + t * 256;
        int row = idx >> 3, seg = idx & 7;
        const void* src = g + (size_t)(row0 + row) * K + k0 + seg * 8;
        cp16(sdst + swz(row * 128 + seg * 16), src);
    }
}

template<bool SPLIT>
__global__ __launch_bounds__(256, 1) void gemm_mma(
    const __nv_bfloat16* __restrict__ Ah, const __nv_bfloat16* __restrict__ Al,
    const __nv_bfloat16* __restrict__ Bh, const __nv_bfloat16* __restrict__ Bl,
    const float* __restrict__ bias, float* __restrict__ Cf,
    __nv_bfloat16* __restrict__ Ch, __nv_bfloat16* __restrict__ Cl,
    int M, int N, int K)
{
    extern __shared__ char smem[];
    const uint32_t sb = smem_u32(smem);
    const int tid  = threadIdx.x;
    const int wid  = tid >> 5, lane = tid & 31;
    const int bm = blockIdx.y * 128, bn = blockIdx.x * 128;
    const int wm = (wid >> 2) * 64, wn = (wid & 3) * 32;
    const int NC = K / GBK;

    // prologue: stages 0,1
#pragma unroll
    for (int s = 0; s < 2; s++) {
        uint32_t st = sb + s * STAGEB;
        load_op(Ah, bm, K, s * GBK, st,             tid);
        load_op(Al, bm, K, s * GBK, st + TILEB,     tid);
        load_op(Bh, bn, K, s * GBK, st + 2 * TILEB, tid);
        load_op(Bl, bn, K, s * GBK, st + 3 * TILEB, tid);
        CP_COMMIT();
    }

    float acc[4][4][4];
#pragma unroll
    for (int i = 0; i < 4; i++)
#pragma unroll
        for (int j = 0; j < 4; j++)
#pragma unroll
            for (int r = 0; r < 4; r++) acc[i][j][r] = 0.0f;

    const int arow = wm + (lane & 15);
    const int brow = wn + (lane & 7) + ((lane >> 4) & 1) * 8;

    for (int c = 0; c < NC; c++) {
        CP_WAIT1();            // chunk c landed
        __syncthreads();       // all warps done computing chunk c-1

        if (c + 2 < NC) {      // pre-issue chunk c+2 into freed buffer
            uint32_t nst = sb + ((c + 2) % STAGES) * STAGEB;
            int k0 = (c + 2) * GBK;
            load_op(Ah, bm, K, k0, nst,             tid);
            load_op(Al, bm, K, k0, nst + TILEB,     tid);
            load_op(Bh, bn, K, k0, nst + 2 * TILEB, tid);
            load_op(Bl, bn, K, k0, nst + 3 * TILEB, tid);
        }
        CP_COMMIT();

        const uint32_t st = sb + (c % STAGES) * STAGEB;
#pragma unroll
        for (int ks = 0; ks < 4; ks++) {
            uint32_t ah[4][4], al[4][4], bh[4][2], bl[4][2];
            const uint32_t ka = (uint32_t)((ks * 2 + (lane >> 4)) * 16);
            const uint32_t kb = (uint32_t)((ks * 2 + ((lane >> 3) & 1)) * 16);
#pragma unroll
            for (int mi = 0; mi < 4; mi++) {
                uint32_t off = swz((uint32_t)(arow + mi * 16) * 128 + ka);
                ldsm4(ah[mi][0], ah[mi][1], ah[mi][2], ah[mi][3], st + off);
                ldsm4(al[mi][0], al[mi][1], al[mi][2], al[mi][3], st + TILEB + off);
            }
#pragma unroll
            for (int n2 = 0; n2 < 2; n2++) {
                uint32_t off = swz((uint32_t)(brow + n2 * 16) * 128 + kb);
                uint32_t r0, r1, r2, r3;
                ldsm4(r0, r1, r2, r3, st + 2 * TILEB + off);
                bh[2 * n2][0] = r0; bh[2 * n2][1] = r1;
                bh[2 * n2 + 1][0] = r2; bh[2 * n2 + 1][1] = r3;
                ldsm4(r0, r1, r2, r3, st + 3 * TILEB + off);
                bl[2 * n2][0] = r0; bl[2 * n2][1] = r1;
                bl[2 * n2 + 1][0] = r2; bl[2 * n2 + 1][1] = r3;
            }
#pragma unroll
            for (int mi = 0; mi < 4; mi++)
#pragma unroll
                for (int nj = 0; nj < 4; nj++) {
                    mma16816(acc[mi][nj], ah[mi], bh[nj]);
                    mma16816(acc[mi][nj], ah[mi], bl[nj]);
                    mma16816(acc[mi][nj], al[mi], bh[nj]);
                }
        }
    }

    const int r0 = bm + wm + (lane >> 2);
    const int c0 = bn + wn + (lane & 3) * 2;
#pragma unroll
    for (int mi = 0; mi < 4; mi++) {
        const int row = r0 + mi * 16;
#pragma unroll
        for (int nj = 0; nj < 4; nj++) {
            const int col = c0 + nj * 8;
            float2 bv = *reinterpret_cast<const float2*>(bias + col);
            float o0 = acc[mi][nj][0] + bv.x, o1 = acc[mi][nj][1] + bv.y;
            float o2 = acc[mi][nj][2] + bv.x, o3 = acc[mi][nj][3] + bv.y;
            if (SPLIT) {
                uint32_t h01, l01, h23, l23;
                split_pack(o0, o1, h01, l01);
                split_pack(o2, o3, h23, l23);
                *reinterpret_cast<uint32_t*>(Ch + (size_t)row * N + col)       = h01;
                *reinterpret_cast<uint32_t*>(Cl + (size_t)row * N + col)       = l01;
                *reinterpret_cast<uint32_t*>(Ch + (size_t)(row + 8) * N + col) = h23;
                *reinterpret_cast<uint32_t*>(Cl + (size_t)(row + 8) * N + col) = l23;
            } else {
                *reinterpret_cast<float2*>(Cf + (size_t)row * N + col)       = make_float2(o0, o1);
                *reinterpret_cast<float2*>(Cf + (size_t)(row + 8) * N + col) = make_float2(o2, o3);
            }
        }
    }
}

// ---------------- flash attention on mma.sync (split bf16) ------------------
// 3-stage KV pipeline, single barrier per tile, loads pre-issued before MMAs.
#define QH_OFF 0
#define QL_OFF (128 * 128)
#define ST_OFF (2 * 128 * 128)       // 32768
#define KHO 0
#define KLO 8192
#define VHO 16384
#define VLO 24576
#define ASTAGE 32768
#define ASTAGES 3
#define ASMEM (ST_OFF + ASTAGES * ASTAGE)  // 131072

__device__ __forceinline__ void load_kv_tile(
    const __nv_bfloat16* __restrict__ qh, const __nv_bfloat16* __restrict__ ql,
    size_t baseK, size_t baseV, int k0, uint32_t st, int tid)
{
#pragma unroll
    for (int t = 0; t < 2; t++) {
        int idx = tid + t * 256;
        int row = idx >> 3, seg = idx & 7;
        size_t gK = baseK + (size_t)(k0 + row) * C3 + seg * 8;
        size_t gV = baseV + (size_t)(k0 + row) * C3 + seg * 8;
        uint32_t off = swz(row * 128 + seg * 16);
        cp16(st + KHO + off, qh + gK);
        cp16(st + KLO + off, ql + gK);
        cp16(st + VHO + off, qh + gV);
        cp16(st + VLO + off, ql + gV);
    }
}

__global__ __launch_bounds__(256) void attn_mma(
    const __nv_bfloat16* __restrict__ qkvh, const __nv_bfloat16* __restrict__ qkvl,
    __nv_bfloat16* __restrict__ yh, __nv_bfloat16* __restrict__ yl)
{
    extern __shared__ char smem[];
    const uint32_t sb = smem_u32(smem);
    const int tid = threadIdx.x;
    const int w = tid >> 5, lane = tid & 31;
    const int qb = (T_ / 128 - 1) - blockIdx.x;   // reversed for balance
    const int h = blockIdx.y, b = blockIdx.z;
    const int q0 = qb * 128;
    const int NT = 2 * (qb + 1);
    const float SCL = 0.125f * 1.4426950408889634f;

    const size_t baseRow = (size_t)b * T_ * C3 + (size_t)h * HS;
    const size_t baseQ = baseRow;
    const size_t baseK = baseRow + C_;
    const size_t baseV = baseRow + 2 * C_;

    // prologue: Q tile + KV stage 0 (group 0), KV stage 1 (group 1)
#pragma unroll
    for (int t = 0; t < 4; t++) {
        int idx = tid + t * 256;
        int row = idx >> 3, seg = idx & 7;
        size_t g = baseQ + (size_t)(q0 + row) * C3 + seg * 8;
        uint32_t off = swz(row * 128 + seg * 16);
        cp16(sb + QH_OFF + off, qkvh + g);
        cp16(sb + QL_OFF + off, qkvl + g);
    }
    load_kv_tile(qkvh, qkvl, baseK, baseV, 0, sb + ST_OFF, tid);
    CP_COMMIT();
    if (NT > 1) load_kv_tile(qkvh, qkvl, baseK, baseV, 64, sb + ST_OFF + ASTAGE, tid);
    CP_COMMIT();

    uint32_t qhf[4][4], qlf[4][4];
    float o[8][4];
#pragma unroll
    for (int i = 0; i < 8; i++)
#pragma unroll
        for (int r = 0; r < 4; r++) o[i][r] = 0.0f;
    float m0 = -1e30f, m1 = -1e30f, l0 = 0.0f, l1 = 0.0f;

    const int qrow_hi = q0 + w * 16 + 15;
    const int r0row = q0 + w * 16 + (lane >> 2);
    const int r1row = r0row + 8;

    for (int c = 0; c < NT; c++) {
        CP_WAIT1();            // tile c landed
        __syncthreads();       // all warps done with tile c-1

        if (c + 2 < NT)        // pre-issue tile c+2 into freed buffer
            load_kv_tile(qkvh, qkvl, baseK, baseV, (c + 2) * 64,
                         sb + ST_OFF + ((c + 2) % ASTAGES) * ASTAGE, tid);
        CP_COMMIT();

        if (c == 0) {   // move Q to registers (a-fragments)
            const int arow = w * 16 + (lane & 15);
#pragma unroll
            for (int ks = 0; ks < 4; ks++) {
                uint32_t ka = (uint32_t)((ks * 2 + (lane >> 4)) * 16);
                uint32_t off = swz((uint32_t)arow * 128 + ka);
                ldsm4(qhf[ks][0], qhf[ks][1], qhf[ks][2], qhf[ks][3], sb + QH_OFF + off);
                ldsm4(qlf[ks][0], qlf[ks][1], qlf[ks][2], qlf[ks][3], sb + QL_OFF + off);
            }
        }

        const int k0 = c * 64;
        const uint32_t st = sb + ST_OFF + (c % ASTAGES) * ASTAGE;

        if (k0 <= qrow_hi) {
            // ---- S = Q @ K^T (split) ----
            float s[8][4];
#pragma unroll
            for (int i = 0; i < 8; i++)
#pragma unroll
                for (int r = 0; r < 4; r++) s[i][r] = 0.0f;

#pragma unroll
            for (int ks = 0; ks < 4; ks++) {
                uint32_t kh[8][2], kl[8][2];
                const uint32_t kb = (uint32_t)((ks * 2 + ((lane >> 3) & 1)) * 16);
                const int brow = (lane & 7) + ((lane >> 4) & 1) * 8;
#pragma unroll
                for (int ng = 0; ng < 4; ng++) {
                    uint32_t off = swz((uint32_t)(ng * 16 + brow) * 128 + kb);
                    uint32_t r0, r1, r2, r3;
                    ldsm4(r0, r1, r2, r3, st + KHO + off);
                    kh[2 * ng][0] = r0; kh[2 * ng][1] = r1;
                    kh[2 * ng + 1][0] = r2; kh[2 * ng + 1][1] = r3;
                    ldsm4(r0, r1, r2, r3, st + KLO + off);
                    kl[2 * ng][0] = r0; kl[2 * ng][1] = r1;
                    kl[2 * ng + 1][0] = r2; kl[2 * ng + 1][1] = r3;
                }
#pragma unroll
                for (int nb = 0; nb < 8; nb++) {
                    mma16816(s[nb], qhf[ks], kh[nb]);
                    mma16816(s[nb], qhf[ks], kl[nb]);
                    mma16816(s[nb], qlf[ks], kh[nb]);
                }
            }

            // ---- online softmax (scaled by log2e) ----
            const bool needmask = (k0 + 63 > q0 + w * 16);
            float mx0 = -1e30f, mx1 = -1e30f;
#pragma unroll
            for (int nb = 0; nb < 8; nb++) {
                float v0 = s[nb][0] * SCL, v1 = s[nb][1] * SCL;
                float v2 = s[nb][2] * SCL, v3 = s[nb][3] * SCL;
                if (needmask) {
                    int key = k0 + nb * 8 + 2 * (lane & 3);
                    if (key     > r0row) v0 = -1e30f;
                    if (key + 1 > r0row) v1 = -1e30f;
                    if (key     > r1row) v2 = -1e30f;
                    if (key + 1 > r1row) v3 = -1e30f;
                }
                s[nb][0] = v0; s[nb][1] = v1; s[nb][2] = v2; s[nb][3] = v3;
                mx0 = fmaxf(mx0, fmaxf(v0, v1));
                mx1 = fmaxf(mx1, fmaxf(v2, v3));
            }
            mx0 = fmaxf(mx0, __shfl_xor_sync(0xffffffffu, mx0, 1));
            mx0 = fmaxf(mx0, __shfl_xor_sync(0xffffffffu, mx0, 2));
            mx1 = fmaxf(mx1, __shfl_xor_sync(0xffffffffu, mx1, 1));
            mx1 = fmaxf(mx1, __shfl_xor_sync(0xffffffffu, mx1, 2));

            const float mn0 = fmaxf(m0, mx0), mn1 = fmaxf(m1, mx1);
            const float a0 = ex2f(m0 - mn0), a1 = ex2f(m1 - mn1);
            m0 = mn0; m1 = mn1;
            l0 *= a0; l1 *= a1;
#pragma unroll
            for (int nb = 0; nb < 8; nb++) {
                float p0 = ex2f(s[nb][0] - m0), p1 = ex2f(s[nb][1] - m0);
                float p2 = ex2f(s[nb][2] - m1), p3 = ex2f(s[nb][3] - m1);
                l0 += p0 + p1; l1 += p2 + p3;
                s[nb][0] = p0; s[nb][1] = p1; s[nb][2] = p2; s[nb][3] = p3;
            }
#pragma unroll
            for (int nd = 0; nd < 8; nd++) {
                o[nd][0] *= a0; o[nd][1] *= a0;
                o[nd][2] *= a1; o[nd][3] *= a1;
            }

            // ---- O += P @ V (split; P from regs, V via ldmatrix.trans) ----
#pragma unroll
            for (int kp = 0; kp < 4; kp++) {
                uint32_t pah[4], pal[4];
                split_pack(s[2 * kp][0],     s[2 * kp][1],     pah[0], pal[0]);
                split_pack(s[2 * kp][2],     s[2 * kp][3],     pah[1], pal[1]);
                split_pack(s[2 * kp + 1][0], s[2 * kp + 1][1], pah[2], pal[2]);
                split_pack(s[2 * kp + 1][2], s[2 * kp + 1][3], pah[3], pal[3]);

                uint32_t vh[8][2], vl[8][2];
                const uint32_t vrow = (uint32_t)(kp * 16 + (lane & 7) + ((lane >> 3) & 1) * 8);
#pragma unroll
                for (int dg = 0; dg < 4; dg++) {
                    uint32_t off = swz(vrow * 128 + dg * 32 + ((lane >> 4) & 1) * 16);
                    uint32_t r0, r1, r2, r3;
                    ldsm4t(r0, r1, r2, r3, st + VHO + off);
                    vh[2 * dg][0] = r0; vh[2 * dg][1] = r1;
                    vh[2 * dg + 1][0] = r2; vh[2 * dg + 1][1] = r3;
                    ldsm4t(r0, r1, r2, r3, st + VLO + off);
                    vl[2 * dg][0] = r0; vl[2 * dg][1] = r1;
                    vl[2 * dg + 1][0] = r2; vl[2 * dg + 1][1] = r3;
                }
#pragma unroll
                for (int nd = 0; nd < 8; nd++) {
                    mma16816(o[nd], pah, vh[nd]);
                    mma16816(o[nd], pah, vl[nd]);
                    mma16816(o[nd], pal, vh[nd]);
                }
            }
        }
    }

    // ---- finalize: reduce l, normalize, write y hi/lo ----
    l0 += __shfl_xor_sync(0xffffffffu, l0, 1);
    l0 += __shfl_xor_sync(0xffffffffu, l0, 2);
    l1 += __shfl_xor_sync(0xffffffffu, l1, 1);
    l1 += __shfl_xor_sync(0xffffffffu, l1, 2);
    const float inv0 = 1.0f / l0, inv1 = 1.0f / l1;

    const size_t ybase = (size_t)b * T_ * C_ + (size_t)h * HS;
#pragma unroll
    for (int nd = 0; nd < 8; nd++) {
        int d = nd * 8 + 2 * (lane & 3);
        size_t i0 = ybase + (size_t)r0row * C_ + d;
        size_t i1 = ybase + (size_t)r1row * C_ + d;
        uint32_t hh, ll;
        split_pack(o[nd][0] * inv0, o[nd][1] * inv0, hh, ll);
        *reinterpret_cast<uint32_t*>(yh + i0) = hh;
        *reinterpret_cast<uint32_t*>(yl + i0) = ll;
        split_pack(o[nd][2] * inv1, o[nd][3] * inv1, hh, ll);
        *reinterpret_cast<uint32_t*>(yh + i1) = hh;
        *reinterpret_cast<uint32_t*>(yl + i1) = ll;
    }
}

// ---------------------------------------------------------------------------
extern "C" void kernel_launch(void* const* d_in, const int* in_sizes, int n_in,
                              void* d_out, int out_size)
{
    const float* x      = (const float*)d_in[0];
    const float* w_attn = (const float*)d_in[1];
    const float* b_attn = (const float*)d_in[2];
    const float* w_proj = (const float*)d_in[3];
    const float* b_proj = (const float*)d_in[4];
    float* out = (float*)d_out;

    __nv_bfloat16 *xh, *xl, *qkvh, *qkvl, *yh, *yl, *wah, *wal, *wph, *wpl;
    cudaGetSymbolAddress((void**)&xh,   g_xh);
    cudaGetSymbolAddress((void**)&xl,   g_xl);
    cudaGetSymbolAddress((void**)&qkvh, g_qkvh);
    cudaGetSymbolAddress((void**)&qkvl, g_qkvl);
    cudaGetSymbolAddress((void**)&yh,   g_yh);
    cudaGetSymbolAddress((void**)&yl,   g_yl);
    cudaGetSymbolAddress((void**)&wah,  g_wah);
    cudaGetSymbolAddress((void**)&wal,  g_wal);
    cudaGetSymbolAddress((void**)&wph,  g_wph);
    cudaGetSymbolAddress((void**)&wpl,  g_wpl);

    cudaFuncSetAttribute(gemm_mma<true>,  cudaFuncAttributeMaxDynamicSharedMemorySize, GSMEM);
    cudaFuncSetAttribute(gemm_mma<false>, cudaFuncAttributeMaxDynamicSharedMemorySize, GSMEM);
    cudaFuncSetAttribute(attn_mma, cudaFuncAttributeMaxDynamicSharedMemorySize, ASMEM);

    // split conversions (inputs only)
    split_cvt<<<(M_ * KD) / (256 * 4), 256>>>(x, xh, xl, M_ * KD);
    split_cvt_T<<<dim3(N1 / 32, KD / 32), 256>>>(w_attn, wah, wal, KD, N1);
    split_cvt_T<<<dim3(C_ / 32, KD / 32), 256>>>(w_proj, wph, wpl, KD, C_);

    // 1) QKV = x @ w_attn + b_attn -> split bf16 qkv  [8192 x 2304]
    gemm_mma<true><<<dim3(N1 / 128, M_ / 128), 256, GSMEM>>>(
        xh, xl, wah, wal, b_attn, nullptr, qkvh, qkvl, M_, N1, KD);

    // 2) causal flash attention -> split bf16 y  [8192 x 768]
    attn_mma<<<dim3(T_ / 128, NH, B_), 256, ASMEM>>>(qkvh, qkvl, yh, yl);

    // 3) out = y @ w_proj + b_proj  [8192 x 768] fp32
    gemm_mma<false><<<dim3(C_ / 128, M_ / 128), 256, GSMEM>>>(
        yh, yl, wph, wpl, b_proj, out, nullptr, nullptr, M_, C_, KD);
}

// round 13
// speedup vs baseline: 1.0224x; 1.0224x over previous
#include <cuda_runtime.h>
#include <cuda_bf16.h>
#include <cstdint>

#define B_  4
#define T_  2048
#define C_  768
#define NH  12
#define HS  64
#define M_  (B_ * T_)          // 8192
#define N1  (3 * C_)           // 2304
#define KD  C_                 // 768
#define C3  (3 * C_)

// ---------------- scratch (__device__ globals; no cudaMalloc) --------------
__device__ __align__(256) __nv_bfloat16 g_xh  [M_ * KD], g_xl  [M_ * KD];
__device__ __align__(256) __nv_bfloat16 g_qkvh[M_ * N1], g_qkvl[M_ * N1];
__device__ __align__(256) __nv_bfloat16 g_yh  [M_ * KD], g_yl  [M_ * KD];
__device__ __align__(256) __nv_bfloat16 g_wah [N1 * KD], g_wal [N1 * KD];  // w_attn^T [N,K]
__device__ __align__(256) __nv_bfloat16 g_wph [C_ * KD], g_wpl [C_ * KD];  // w_proj^T [N,K]

// ---------------- helpers ---------------------------------------------------
__device__ __forceinline__ uint32_t smem_u32(const void* p) {
    uint32_t a;
    asm("{ .reg .u64 t; cvta.to.shared.u64 t, %1; cvt.u32.u64 %0, t; }"
        : "=r"(a) : "l"(p));
    return a;
}
__device__ __forceinline__ uint32_t swz(uint32_t off) {     // SW128
    return off ^ ((off >> 3) & 0x70);
}
__device__ __forceinline__ void cp16(uint32_t dst, const void* src) {
    asm volatile("cp.async.cg.shared.global [%0], [%1], 16;" :: "r"(dst), "l"(src));
}
#define CP_COMMIT() asm volatile("cp.async.commit_group;" ::: "memory")
#define CP_WAIT2()  asm volatile("cp.async.wait_group 2;" ::: "memory")
#define CP_WAIT1()  asm volatile("cp.async.wait_group 1;" ::: "memory")

__device__ __forceinline__ void ldsm4(uint32_t& r0, uint32_t& r1,
                                      uint32_t& r2, uint32_t& r3, uint32_t a) {
    asm volatile("ldmatrix.sync.aligned.m8n8.x4.shared.b16 {%0,%1,%2,%3}, [%4];"
                 : "=r"(r0), "=r"(r1), "=r"(r2), "=r"(r3) : "r"(a));
}
__device__ __forceinline__ void ldsm4t(uint32_t& r0, uint32_t& r1,
                                       uint32_t& r2, uint32_t& r3, uint32_t a) {
    asm volatile("ldmatrix.sync.aligned.m8n8.x4.trans.shared.b16 {%0,%1,%2,%3}, [%4];"
                 : "=r"(r0), "=r"(r1), "=r"(r2), "=r"(r3) : "r"(a));
}
__device__ __forceinline__ void mma16816(float* d, const uint32_t* a,
                                         const uint32_t* b) {
    asm volatile("mma.sync.aligned.m16n8k16.row.col.f32.bf16.bf16.f32 "
                 "{%0,%1,%2,%3}, {%4,%5,%6,%7}, {%8,%9}, {%0,%1,%2,%3};"
                 : "+f"(d[0]), "+f"(d[1]), "+f"(d[2]), "+f"(d[3])
                 : "r"(a[0]), "r"(a[1]), "r"(a[2]), "r"(a[3]),
                   "r"(b[0]), "r"(b[1]));
}
__device__ __forceinline__ float ex2f(float x) {
    float y; asm("ex2.approx.f32 %0, %1;" : "=f"(y) : "f"(x)); return y;
}
__device__ __forceinline__ void split_pack(float a, float b,
                                           uint32_t& hi, uint32_t& lo) {
    __nv_bfloat16 ha = __float2bfloat16(a), hb = __float2bfloat16(b);
    __nv_bfloat16 la = __float2bfloat16(a - __bfloat162float(ha));
    __nv_bfloat16 lb = __float2bfloat16(b - __bfloat162float(hb));
    __nv_bfloat162 H(ha, hb), L(la, lb);
    hi = *reinterpret_cast<uint32_t*>(&H);
    lo = *reinterpret_cast<uint32_t*>(&L);
}

// ---------------- split conversion kernels ---------------------------------
__global__ __launch_bounds__(256) void split_cvt(
    const float* __restrict__ in, __nv_bfloat16* __restrict__ hi,
    __nv_bfloat16* __restrict__ lo, int n)
{
    int idx = (blockIdx.x * 256 + threadIdx.x) * 4;
    if (idx >= n) return;
    float4 v = *reinterpret_cast<const float4*>(in + idx);
    __nv_bfloat16 h0 = __float2bfloat16(v.x), h1 = __float2bfloat16(v.y);
    __nv_bfloat16 h2 = __float2bfloat16(v.z), h3 = __float2bfloat16(v.w);
    __nv_bfloat16 l0 = __float2bfloat16(v.x - __bfloat162float(h0));
    __nv_bfloat16 l1 = __float2bfloat16(v.y - __bfloat162float(h1));
    __nv_bfloat16 l2 = __float2bfloat16(v.z - __bfloat162float(h2));
    __nv_bfloat16 l3 = __float2bfloat16(v.w - __bfloat162float(h3));
    *reinterpret_cast<__nv_bfloat162*>(hi + idx)     = __nv_bfloat162(h0, h1);
    *reinterpret_cast<__nv_bfloat162*>(hi + idx + 2) = __nv_bfloat162(h2, h3);
    *reinterpret_cast<__nv_bfloat162*>(lo + idx)     = __nv_bfloat162(l0, l1);
    *reinterpret_cast<__nv_bfloat162*>(lo + idx + 2) = __nv_bfloat162(l2, l3);
}

// transpose + split: in [K,N] row-major -> hi/lo [N,K]
__global__ __launch_bounds__(256) void split_cvt_T(
    const float* __restrict__ in, __nv_bfloat16* __restrict__ hi,
    __nv_bfloat16* __restrict__ lo, int K, int N)
{
    __shared__ float t[32][33];
    const int tx = threadIdx.x & 31, ty = threadIdx.x >> 5;
    const int k0 = blockIdx.y * 32, n0 = blockIdx.x * 32;
#pragma unroll
    for (int r = 0; r < 32; r += 8)
        t[ty + r][tx] = in[(size_t)(k0 + ty + r) * N + n0 + tx];
    __syncthreads();
#pragma unroll
    for (int r = 0; r < 32; r += 8) {
        float v = t[tx][ty + r];
        __nv_bfloat16 h = __float2bfloat16(v);
        __nv_bfloat16 l = __float2bfloat16(v - __bfloat162float(h));
        size_t o = (size_t)(n0 + ty + r) * K + k0 + tx;
        hi[o] = h; lo[o] = l;
    }
}

// ---------------- mma.sync split-bf16 GEMM ----------------------------------
// R10 pipeline skeleton; MMAs issued TERM-MAJOR so consecutive MMAs never
// share an accumulator (RAW distance 16).
#define GBK   64
#define TILEB (128 * 128)
#define STAGEB (4 * TILEB)
#define STAGES 3
#define GSMEM (STAGES * STAGEB)  // 192KB

__device__ __forceinline__ void load_op(
    const __nv_bfloat16* __restrict__ g, int row0, int K, int k0,
    uint32_t sdst, int tid)
{
#pragma unroll
    for (int t = 0; t < 4; t++) {
        int idx = tid + t * 256;
        int row = idx >> 3, seg = idx & 7;
        const void* src = g + (size_t)(row0 + row) * K + k0 + seg * 8;
        cp16(sdst + swz(row * 128 + seg * 16), src);
    }
}

template<bool SPLIT>
__global__ __launch_bounds__(256, 1) void gemm_mma(
    const __nv_bfloat16* __restrict__ Ah, const __nv_bfloat16* __restrict__ Al,
    const __nv_bfloat16* __restrict__ Bh, const __nv_bfloat16* __restrict__ Bl,
    const float* __restrict__ bias, float* __restrict__ Cf,
    __nv_bfloat16* __restrict__ Ch, __nv_bfloat16* __restrict__ Cl,
    int M, int N, int K)
{
    extern __shared__ char smem[];
    const uint32_t sb = smem_u32(smem);
    const int tid  = threadIdx.x;
    const int wid  = tid >> 5, lane = tid & 31;
    const int bm = blockIdx.y * 128, bn = blockIdx.x * 128;
    const int wm = (wid >> 2) * 64, wn = (wid & 3) * 32;
    const int NC = K / GBK;

#pragma unroll
    for (int s = 0; s < STAGES; s++) {
        uint32_t st = sb + s * STAGEB;
        load_op(Ah, bm, K, s * GBK, st,             tid);
        load_op(Al, bm, K, s * GBK, st + TILEB,     tid);
        load_op(Bh, bn, K, s * GBK, st + 2 * TILEB, tid);
        load_op(Bl, bn, K, s * GBK, st + 3 * TILEB, tid);
        CP_COMMIT();
    }

    float acc[4][4][4];
#pragma unroll
    for (int i = 0; i < 4; i++)
#pragma unroll
        for (int j = 0; j < 4; j++)
#pragma unroll
            for (int r = 0; r < 4; r++) acc[i][j][r] = 0.0f;

    const int arow = wm + (lane & 15);
    const int brow = wn + (lane & 7) + ((lane >> 4) & 1) * 8;

    for (int c = 0; c < NC; c++) {
        CP_WAIT2();
        __syncthreads();
        const uint32_t st = sb + (c % STAGES) * STAGEB;

#pragma unroll
        for (int ks = 0; ks < 4; ks++) {
            uint32_t ah[4][4], al[4][4], bh[4][2], bl[4][2];
            const uint32_t ka = (uint32_t)((ks * 2 + (lane >> 4)) * 16);
            const uint32_t kb = (uint32_t)((ks * 2 + ((lane >> 3) & 1)) * 16);
#pragma unroll
            for (int mi = 0; mi < 4; mi++) {
                uint32_t off = swz((uint32_t)(arow + mi * 16) * 128 + ka);
                ldsm4(ah[mi][0], ah[mi][1], ah[mi][2], ah[mi][3], st + off);
                ldsm4(al[mi][0], al[mi][1], al[mi][2], al[mi][3], st + TILEB + off);
            }
#pragma unroll
            for (int n2 = 0; n2 < 2; n2++) {
                uint32_t off = swz((uint32_t)(brow + n2 * 16) * 128 + kb);
                uint32_t r0, r1, r2, r3;
                ldsm4(r0, r1, r2, r3, st + 2 * TILEB + off);
                bh[2 * n2][0] = r0; bh[2 * n2][1] = r1;
                bh[2 * n2 + 1][0] = r2; bh[2 * n2 + 1][1] = r3;
                ldsm4(r0, r1, r2, r3, st + 3 * TILEB + off);
                bl[2 * n2][0] = r0; bl[2 * n2][1] = r1;
                bl[2 * n2 + 1][0] = r2; bl[2 * n2 + 1][1] = r3;
            }
            // term-major: 16 independent MMAs per pass (RAW distance 16)
#pragma unroll
            for (int mi = 0; mi < 4; mi++)
#pragma unroll
                for (int nj = 0; nj < 4; nj++)
                    mma16816(acc[mi][nj], ah[mi], bh[nj]);
#pragma unroll
            for (int mi = 0; mi < 4; mi++)
#pragma unroll
                for (int nj = 0; nj < 4; nj++)
                    mma16816(acc[mi][nj], ah[mi], bl[nj]);
#pragma unroll
            for (int mi = 0; mi < 4; mi++)
#pragma unroll
                for (int nj = 0; nj < 4; nj++)
                    mma16816(acc[mi][nj], al[mi], bh[nj]);
        }
        __syncthreads();

        if (c + STAGES < NC) {
            uint32_t nst = sb + (c % STAGES) * STAGEB;
            int k0 = (c + STAGES) * GBK;
            load_op(Ah, bm, K, k0, nst,             tid);
            load_op(Al, bm, K, k0, nst + TILEB,     tid);
            load_op(Bh, bn, K, k0, nst + 2 * TILEB, tid);
            load_op(Bl, bn, K, k0, nst + 3 * TILEB, tid);
        }
        CP_COMMIT();
    }

    const int r0 = bm + wm + (lane >> 2);
    const int c0 = bn + wn + (lane & 3) * 2;
#pragma unroll
    for (int mi = 0; mi < 4; mi++) {
        const int row = r0 + mi * 16;
#pragma unroll
        for (int nj = 0; nj < 4; nj++) {
            const int col = c0 + nj * 8;
            float2 bv = *reinterpret_cast<const float2*>(bias + col);
            float o0 = acc[mi][nj][0] + bv.x, o1 = acc[mi][nj][1] + bv.y;
            float o2 = acc[mi][nj][2] + bv.x, o3 = acc[mi][nj][3] + bv.y;
            if (SPLIT) {
                uint32_t h01, l01, h23, l23;
                split_pack(o0, o1, h01, l01);
                split_pack(o2, o3, h23, l23);
                *reinterpret_cast<uint32_t*>(Ch + (size_t)row * N + col)       = h01;
                *reinterpret_cast<uint32_t*>(Cl + (size_t)row * N + col)       = l01;
                *reinterpret_cast<uint32_t*>(Ch + (size_t)(row + 8) * N + col) = h23;
                *reinterpret_cast<uint32_t*>(Cl + (size_t)(row + 8) * N + col) = l23;
            } else {
                *reinterpret_cast<float2*>(Cf + (size_t)row * N + col)       = make_float2(o0, o1);
                *reinterpret_cast<float2*>(Cf + (size_t)(row + 8) * N + col) = make_float2(o2, o3);
            }
        }
    }
}

// ---------------- flash attention on mma.sync (split bf16) ------------------
// R10 skeleton (2-stage double buffer); MMAs term-major (RAW distance 8).
#define QH_OFF 0
#define QL_OFF (128 * 128)
#define ST_OFF (2 * 128 * 128)       // 32768
#define KHO 0
#define KLO 8192
#define VHO 16384
#define VLO 24576
#define ASTAGE 32768
#define ASMEM (ST_OFF + 2 * ASTAGE)  // 98304

__device__ __forceinline__ void load_kv_tile(
    const __nv_bfloat16* __restrict__ qh, const __nv_bfloat16* __restrict__ ql,
    size_t baseK, size_t baseV, int k0, uint32_t st, int tid)
{
#pragma unroll
    for (int t = 0; t < 2; t++) {
        int idx = tid + t * 256;
        int row = idx >> 3, seg = idx & 7;
        size_t gK = baseK + (size_t)(k0 + row) * C3 + seg * 8;
        size_t gV = baseV + (size_t)(k0 + row) * C3 + seg * 8;
        uint32_t off = swz(row * 128 + seg * 16);
        cp16(st + KHO + off, qh + gK);
        cp16(st + KLO + off, ql + gK);
        cp16(st + VHO + off, qh + gV);
        cp16(st + VLO + off, ql + gV);
    }
}

__global__ __launch_bounds__(256) void attn_mma(
    const __nv_bfloat16* __restrict__ qkvh, const __nv_bfloat16* __restrict__ qkvl,
    __nv_bfloat16* __restrict__ yh, __nv_bfloat16* __restrict__ yl)
{
    extern __shared__ char smem[];
    const uint32_t sb = smem_u32(smem);
    const int tid = threadIdx.x;
    const int w = tid >> 5, lane = tid & 31;
    const int qb = (T_ / 128 - 1) - blockIdx.x;   // reversed for balance
    const int h = blockIdx.y, b = blockIdx.z;
    const int q0 = qb * 128;
    const int NT = 2 * (qb + 1);
    const float SCL = 0.125f * 1.4426950408889634f;

    const size_t baseRow = (size_t)b * T_ * C3 + (size_t)h * HS;
    const size_t baseQ = baseRow;
    const size_t baseK = baseRow + C_;
    const size_t baseV = baseRow + 2 * C_;

#pragma unroll
    for (int t = 0; t < 4; t++) {
        int idx = tid + t * 256;
        int row = idx >> 3, seg = idx & 7;
        size_t g = baseQ + (size_t)(q0 + row) * C3 + seg * 8;
        uint32_t off = swz(row * 128 + seg * 16);
        cp16(sb + QH_OFF + off, qkvh + g);
        cp16(sb + QL_OFF + off, qkvl + g);
    }
    load_kv_tile(qkvh, qkvl, baseK, baseV, 0, sb + ST_OFF, tid);
    CP_COMMIT();
    if (NT > 1) load_kv_tile(qkvh, qkvl, baseK, baseV, 64, sb + ST_OFF + ASTAGE, tid);
    CP_COMMIT();

    uint32_t qhf[4][4], qlf[4][4];
    float o[8][4];
#pragma unroll
    for (int i = 0; i < 8; i++)
#pragma unroll
        for (int r = 0; r < 4; r++) o[i][r] = 0.0f;
    float m0 = -1e30f, m1 = -1e30f, l0 = 0.0f, l1 = 0.0f;

    const int qrow_hi = q0 + w * 16 + 15;
    const int r0row = q0 + w * 16 + (lane >> 2);
    const int r1row = r0row + 8;

    for (int c = 0; c < NT; c++) {
        CP_WAIT1();
        __syncthreads();

        if (c == 0) {   // move Q to registers (a-fragments)
            const int arow = w * 16 + (lane & 15);
#pragma unroll
            for (int ks = 0; ks < 4; ks++) {
                uint32_t ka = (uint32_t)((ks * 2 + (lane >> 4)) * 16);
                uint32_t off = swz((uint32_t)arow * 128 + ka);
                ldsm4(qhf[ks][0], qhf[ks][1], qhf[ks][2], qhf[ks][3], sb + QH_OFF + off);
                ldsm4(qlf[ks][0], qlf[ks][1], qlf[ks][2], qlf[ks][3], sb + QL_OFF + off);
            }
        }

        const int k0 = c * 64;
        const uint32_t st = sb + ST_OFF + (c & 1) * ASTAGE;

        if (k0 <= qrow_hi) {
            // ---- S = Q @ K^T (split, term-major) ----
            float s[8][4];
#pragma unroll
            for (int i = 0; i < 8; i++)
#pragma unroll
                for (int r = 0; r < 4; r++) s[i][r] = 0.0f;

#pragma unroll
            for (int ks = 0; ks < 4; ks++) {
                uint32_t kh[8][2], kl[8][2];
                const uint32_t kb = (uint32_t)((ks * 2 + ((lane >> 3) & 1)) * 16);
                const int brow = (lane & 7) + ((lane >> 4) & 1) * 8;
#pragma unroll
                for (int ng = 0; ng < 4; ng++) {
                    uint32_t off = swz((uint32_t)(ng * 16 + brow) * 128 + kb);
                    uint32_t r0, r1, r2, r3;
                    ldsm4(r0, r1, r2, r3, st + KHO + off);
                    kh[2 * ng][0] = r0; kh[2 * ng][1] = r1;
                    kh[2 * ng + 1][0] = r2; kh[2 * ng + 1][1] = r3;
                    ldsm4(r0, r1, r2, r3, st + KLO + off);
                    kl[2 * ng][0] = r0; kl[2 * ng][1] = r1;
                    kl[2 * ng + 1][0] = r2; kl[2 * ng + 1][1] = r3;
                }
#pragma unroll
                for (int nb = 0; nb < 8; nb++)
                    mma16816(s[nb], qhf[ks], kh[nb]);
#pragma unroll
                for (int nb = 0; nb < 8; nb++)
                    mma16816(s[nb], qhf[ks], kl[nb]);
#pragma unroll
                for (int nb = 0; nb < 8; nb++)
                    mma16816(s[nb], qlf[ks], kh[nb]);
            }

            // ---- online softmax (scaled by log2e) ----
            const bool needmask = (k0 + 63 > q0 + w * 16);
            float mx0 = -1e30f, mx1 = -1e30f;
#pragma unroll
            for (int nb = 0; nb < 8; nb++) {
                float v0 = s[nb][0] * SCL, v1 = s[nb][1] * SCL;
                float v2 = s[nb][2] * SCL, v3 = s[nb][3] * SCL;
                if (needmask) {
                    int key = k0 + nb * 8 + 2 * (lane & 3);
                    if (key     > r0row) v0 = -1e30f;
                    if (key + 1 > r0row) v1 = -1e30f;
                    if (key     > r1row) v2 = -1e30f;
                    if (key + 1 > r1row) v3 = -1e30f;
                }
                s[nb][0] = v0; s[nb][1] = v1; s[nb][2] = v2; s[nb][3] = v3;
                mx0 = fmaxf(mx0, fmaxf(v0, v1));
                mx1 = fmaxf(mx1, fmaxf(v2, v3));
            }
            mx0 = fmaxf(mx0, __shfl_xor_sync(0xffffffffu, mx0, 1));
            mx0 = fmaxf(mx0, __shfl_xor_sync(0xffffffffu, mx0, 2));
            mx1 = fmaxf(mx1, __shfl_xor_sync(0xffffffffu, mx1, 1));
            mx1 = fmaxf(mx1, __shfl_xor_sync(0xffffffffu, mx1, 2));

            const float mn0 = fmaxf(m0, mx0), mn1 = fmaxf(m1, mx1);
            const float a0 = ex2f(m0 - mn0), a1 = ex2f(m1 - mn1);
            m0 = mn0; m1 = mn1;
            l0 *= a0; l1 *= a1;
#pragma unroll
            for (int nb = 0; nb < 8; nb++) {
                float p0 = ex2f(s[nb][0] - m0), p1 = ex2f(s[nb][1] - m0);
                float p2 = ex2f(s[nb][2] - m1), p3 = ex2f(s[nb][3] - m1);
                l0 += p0 + p1; l1 += p2 + p3;
                s[nb][0] = p0; s[nb][1] = p1; s[nb][2] = p2; s[nb][3] = p3;
            }
#pragma unroll
            for (int nd = 0; nd < 8; nd++) {
                o[nd][0] *= a0; o[nd][1] *= a0;
                o[nd][2] *= a1; o[nd][3] *= a1;
            }

            // ---- O += P @ V (split, term-major) ----
#pragma unroll
            for (int kp = 0; kp < 4; kp++) {
                uint32_t pah[4], pal[4];
                split_pack(s[2 * kp][0],     s[2 * kp][1],     pah[0], pal[0]);
                split_pack(s[2 * kp][2],     s[2 * kp][3],     pah[1], pal[1]);
                split_pack(s[2 * kp + 1][0], s[2 * kp + 1][1], pah[2], pal[2]);
                split_pack(s[2 * kp + 1][2], s[2 * kp + 1][3], pah[3], pal[3]);

                uint32_t vh[8][2], vl[8][2];
                const uint32_t vrow = (uint32_t)(kp * 16 + (lane & 7) + ((lane >> 3) & 1) * 8);
#pragma unroll
                for (int dg = 0; dg < 4; dg++) {
                    uint32_t off = swz(vrow * 128 + dg * 32 + ((lane >> 4) & 1) * 16);
                    uint32_t r0, r1, r2, r3;
                    ldsm4t(r0, r1, r2, r3, st + VHO + off);
                    vh[2 * dg][0] = r0; vh[2 * dg][1] = r1;
                    vh[2 * dg + 1][0] = r2; vh[2 * dg + 1][1] = r3;
                    ldsm4t(r0, r1, r2, r3, st + VLO + off);
                    vl[2 * dg][0] = r0; vl[2 * dg][1] = r1;
                    vl[2 * dg + 1][0] = r2; vl[2 * dg + 1][1] = r3;
                }
#pragma unroll
                for (int nd = 0; nd < 8; nd++)
                    mma16816(o[nd], pah, vh[nd]);
#pragma unroll
                for (int nd = 0; nd < 8; nd++)
                    mma16816(o[nd], pah, vl[nd]);
#pragma unroll
                for (int nd = 0; nd < 8; nd++)
                    mma16816(o[nd], pal, vh[nd]);
            }
        }

        __syncthreads();
        if (c + 2 < NT)
            load_kv_tile(qkvh, qkvl, baseK, baseV, (c + 2) * 64,
                         sb + ST_OFF + (c & 1) * ASTAGE, tid);
        CP_COMMIT();
    }

    // ---- finalize: reduce l, normalize, write y hi/lo ----
    l0 += __shfl_xor_sync(0xffffffffu, l0, 1);
    l0 += __shfl_xor_sync(0xffffffffu, l0, 2);
    l1 += __shfl_xor_sync(0xffffffffu, l1, 1);
    l1 += __shfl_xor_sync(0xffffffffu, l1, 2);
    const float inv0 = 1.0f / l0, inv1 = 1.0f / l1;

    const size_t ybase = (size_t)b * T_ * C_ + (size_t)h * HS;
#pragma unroll
    for (int nd = 0; nd < 8; nd++) {
        int d = nd * 8 + 2 * (lane & 3);
        size_t i0 = ybase + (size_t)r0row * C_ + d;
        size_t i1 = ybase + (size_t)r1row * C_ + d;
        uint32_t hh, ll;
        split_pack(o[nd][0] * inv0, o[nd][1] * inv0, hh, ll);
        *reinterpret_cast<uint32_t*>(yh + i0) = hh;
        *reinterpret_cast<uint32_t*>(yl + i0) = ll;
        split_pack(o[nd][2] * inv1, o[nd][3] * inv1, hh, ll);
        *reinterpret_cast<uint32_t*>(yh + i1) = hh;
        *reinterpret_cast<uint32_t*>(yl + i1) = ll;
    }
}

// ---------------------------------------------------------------------------
extern "C" void kernel_launch(void* const* d_in, const int* in_sizes, int n_in,
                              void* d_out, int out_size)
{
    const float* x      = (const float*)d_in[0];
    const float* w_attn = (const float*)d_in[1];
    const float* b_attn = (const float*)d_in[2];
    const float* w_proj = (const float*)d_in[3];
    const float* b_proj = (const float*)d_in[4];
    float* out = (float*)d_out;

    __nv_bfloat16 *xh, *xl, *qkvh, *qkvl, *yh, *yl, *wah, *wal, *wph, *wpl;
    cudaGetSymbolAddress((void**)&xh,   g_xh);
    cudaGetSymbolAddress((void**)&xl,   g_xl);
    cudaGetSymbolAddress((void**)&qkvh, g_qkvh);
    cudaGetSymbolAddress((void**)&qkvl, g_qkvl);
    cudaGetSymbolAddress((void**)&yh,   g_yh);
    cudaGetSymbolAddress((void**)&yl,   g_yl);
    cudaGetSymbolAddress((void**)&wah,  g_wah);
    cudaGetSymbolAddress((void**)&wal,  g_wal);
    cudaGetSymbolAddress((void**)&wph,  g_wph);
    cudaGetSymbolAddress((void**)&wpl,  g_wpl);

    cudaFuncSetAttribute(gemm_mma<true>,  cudaFuncAttributeMaxDynamicSharedMemorySize, GSMEM);
    cudaFuncSetAttribute(gemm_mma<false>, cudaFuncAttributeMaxDynamicSharedMemorySize, GSMEM);
    cudaFuncSetAttribute(attn_mma, cudaFuncAttributeMaxDynamicSharedMemorySize, ASMEM);

    // split conversions (inputs only)
    split_cvt<<<(M_ * KD) / (256 * 4), 256>>>(x, xh, xl, M_ * KD);
    split_cvt_T<<<dim3(N1 / 32, KD / 32), 256>>>(w_attn, wah, wal, KD, N1);
    split_cvt_T<<<dim3(C_ / 32, KD / 32), 256>>>(w_proj, wph, wpl, KD, C_);

    // 1) QKV = x @ w_attn + b_attn -> split bf16 qkv  [8192 x 2304]
    gemm_mma<true><<<dim3(N1 / 128, M_ / 128), 256, GSMEM>>>(
        xh, xl, wah, wal, b_attn, nullptr, qkvh, qkvl, M_, N1, KD);

    // 2) causal flash attention -> split bf16 y  [8192 x 768]
    attn_mma<<<dim3(T_ / 128, NH, B_), 256, ASMEM>>>(qkvh, qkvl, yh, yl);

    // 3) out = y @ w_proj + b_proj  [8192 x 768] fp32
    gemm_mma<false><<<dim3(C_ / 128, M_ / 128), 256, GSMEM>>>(
        yh, yl, wph, wpl, b_proj, out, nullptr, nullptr, M_, C_, KD);
}